// round 7
// baseline (speedup 1.0000x reference)
#include <cuda_runtime.h>

// ============================================================================
// 2-layer tanh RNN, B=32, L=2048, H=512 — v6: warp-autonomous quarter-pipelined.
//
// 128 persistent CTAs (1/SM):
//   CTA 0..63   : layer 0 (group A), output columns [cta*8, cta*8+8)
//   CTA 64..127 : layer 1 (group B), columns [(cta-64)*8, ...)
// Weight slices in SMEM all run (lane-interleaved, conflict-free LDS.128).
// K mapping: lane ln owns k = 128*i4 + 4*ln + e  (i4 = K-quarter, e in 0..3).
//
// Sync v6 — NO CTA-wide barriers in the steady-state loop:
//   flags: g_flagA[t][q], g_flagB[t][q]  (q = col/K quarter, 16 CTAs each)
//   producer: each WARP, after its own STGs: __syncwarp -> lane0
//             red.release.gpu.add. Target per flag = 16 CTAs x 8 warps = 128.
//   consumer: each warp polls ld.acquire.gpu (32 lanes, same address ->
//             one coalesced request) on the flag guarding the K-quarter it
//             is about to accumulate. Warps free-run; skew bounded by flags.
// Quarter gating staggers consumer needs: last quarter has ~3x256 FMA2 of
// slack to absorb producer stragglers.
//
// Dataflow: L0 h -> 4-slot global ring (reuse gated on flagB[t-4]);
// L1 h -> d_out directly. Cross-SM reads via __ldcg.
// Compute: fp32 packed fma.rn.f32x2 (512 FMA2/thread/step), numerics as v2-v5.
// ============================================================================

#define BB 32
#define LL 2048
#define HH 512
#define GA 64
#define GB 64
#define NTHR 256

__device__ float g_ring[4 * BB * HH];   // layer-0 h ring, 256 KB
__device__ int   g_flagA[4 * LL];       // [t*4 + q] : A quarter-q warps done t
__device__ int   g_flagB[4 * LL];       // [t*4 + q] : B quarter-q warps done t

// Warp-collective wait: all lanes load the same flag (coalesces to one
// request); exit only when every lane's own acquire observed >= tgt.
__device__ __forceinline__ void warp_wait(const int* p, int tgt) {
    int v;
    do {
        asm volatile("ld.acquire.gpu.global.b32 %0, [%1];"
                     : "=r"(v) : "l"(p) : "memory");
    } while (!__all_sync(0xffffffffu, v >= tgt));
}
__device__ __forceinline__ void rel_add(int* p) {
    asm volatile("red.release.gpu.global.add.u32 [%0], %1;"
                 :: "l"(p), "r"(1u) : "memory");
}

#define FMA2(d, a, w) asm volatile("fma.rn.f32x2 %0, %1, %2, %0;" \
                                   : "+l"(d) : "l"(a), "l"(w))

__device__ __forceinline__ unsigned long long pack2(float v) {
    unsigned long long r;
    asm("mov.b64 %0, {%1,%1};" : "=l"(r) : "f"(v));
    return r;
}

__global__ void zero_flags_kernel() {
    int i = blockIdx.x * blockDim.x + threadIdx.x;
    if (i < 4 * LL) { g_flagA[i] = 0; g_flagB[i] = 0; }
}

// Accumulate ONE K-quarter (i4) of one side into acc[16].
// acc[b*4+q] packs output columns (2q,2q+1) for batch row b0+b.
// Weights: wA cols 0-3, wB cols 4-7; index [(i4*4+e)*32+ln] = k = 128*i4+4*ln+e.
__device__ __forceinline__ void accum_q(
    unsigned long long acc[16],
    const ulonglong2* __restrict__ wA, const ulonglong2* __restrict__ wB,
    const float* __restrict__ p, long long stride, int b0, int ln,
    int i4, bool cg)
{
    float4 v[4];
    #pragma unroll
    for (int b = 0; b < 4; b++) {
        const float4* a = (const float4*)(p + (long long)(b0 + b) * stride
                                          + 128 * i4 + 4 * ln);
        v[b] = cg ? __ldcg(a) : *a;
    }
    #pragma unroll
    for (int e = 0; e < 4; e++) {
        ulonglong2 a  = wA[(i4 * 4 + e) * 32 + ln];
        ulonglong2 bq = wB[(i4 * 4 + e) * 32 + ln];
        #pragma unroll
        for (int b = 0; b < 4; b++) {
            float xv = (e == 0) ? v[b].x : (e == 1) ? v[b].y
                     : (e == 2) ? v[b].z : v[b].w;
            unsigned long long xp = pack2(xv);
            FMA2(acc[b * 4 + 0], xp, a.x);
            FMA2(acc[b * 4 + 1], xp, a.y);
            FMA2(acc[b * 4 + 2], xp, bq.x);
            FMA2(acc[b * 4 + 3], xp, bq.y);
        }
    }
}

__global__ __launch_bounds__(NTHR, 1) void rnn_kernel(
    const float* __restrict__ x,   const float* __restrict__ h0in,
    const float* __restrict__ Wi,  const float* __restrict__ bi,
    const float* __restrict__ Wh,  const float* __restrict__ bh,
    float* __restrict__ out, int write_final)
{
    extern __shared__ float smem[];
    ulonglong2* sWiA = (ulonglong2*)smem;      // [512] Wi cols 0-3 (16B each)
    ulonglong2* sWiB = sWiA + HH;              // [512] Wi cols 4-7
    ulonglong2* sWhA = sWiB + HH;
    ulonglong2* sWhB = sWhA + HH;
    float*      red  = (float*)(sWhB + HH);    // [8 warps][32][33]

    const int  cta   = blockIdx.x;
    const bool isA   = (cta < GA);
    const int  layer = isA ? 0 : 1;
    const int  lcta  = isA ? cta : cta - GA;
    const int  c0    = lcta * 8;
    const int  qme   = lcta >> 4;              // my column quarter
    const int  tid   = threadIdx.x;
    const int  w     = tid >> 5;
    const int  ln    = tid & 31;

    // ---- stage weight slices once: idx(k) = ((k>>7)*4 + (k&3))*32 + ((k>>2)&31)
    {
        const float* wi_g = Wi + (size_t)layer * HH * HH + c0;
        const float* wh_g = Wh + (size_t)layer * HH * HH + c0;
        for (int k = tid; k < HH; k += NTHR) {
            int idx = ((k >> 7) * 4 + (k & 3)) * 32 + ((k >> 2) & 31);
            const ulonglong2* ri = (const ulonglong2*)(wi_g + (size_t)k * HH);
            const ulonglong2* rh = (const ulonglong2*)(wh_g + (size_t)k * HH);
            sWiA[idx] = ri[0];  sWiB[idx] = ri[1];
            sWhA[idx] = rh[0];  sWhB[idx] = rh[1];
        }
    }
    __syncthreads();   // one-time; no CTA-wide barriers after this

    const int   myb  = w * 4 + (ln >> 3);
    const int   myc  = c0 + (ln & 7);
    const float bias = bi[layer * HH + myc] + bh[layer * HH + myc];
    const int   b0   = w * 4;
    float* redw = red + w * (32 * 33);

    int* myflag = (isA ? g_flagA : g_flagB);

    #pragma unroll 1
    for (int t = 0; t < LL; t++) {
        unsigned long long acc[16];
        #pragma unroll
        for (int i = 0; i < 16; i++) acc[i] = 0ull;

        if (isA) {
            // x-side (ungated) first — hides waits below.
            const float* px = x + (long long)t * HH;
            #pragma unroll
            for (int q = 0; q < 4; q++)
                accum_q(acc, sWiA, sWiB, px, (long long)LL * HH, b0, ln, q, false);
            // hidden side, quarter-gated on own group's t-1.
            if (t == 0) {
                #pragma unroll
                for (int q = 0; q < 4; q++)
                    accum_q(acc, sWhA, sWhB, h0in, HH, b0, ln, q, false);
            } else {
                const float* ph = g_ring + ((t - 1) & 3) * (BB * HH);
                #pragma unroll
                for (int q = 0; q < 4; q++) {
                    warp_wait(&g_flagA[(t - 1) * 4 + q], 128);
                    accum_q(acc, sWhA, sWhB, ph, HH, b0, ln, q, true);
                }
            }
        } else {
            // own hidden side first (earlier available than A's step-t flag).
            if (t == 0) {
                #pragma unroll
                for (int q = 0; q < 4; q++)
                    accum_q(acc, sWhA, sWhB, h0in + BB * HH, HH, b0, ln, q, false);
            } else {
                const float* ph = out + (long long)(t - 1) * HH;
                #pragma unroll
                for (int q = 0; q < 4; q++) {
                    warp_wait(&g_flagB[(t - 1) * 4 + q], 128);
                    accum_q(acc, sWhA, sWhB, ph, (long long)LL * HH, b0, ln, q, true);
                }
            }
            // layer-0 output of step t from the ring, quarter-gated.
            const float* pr = g_ring + (t & 3) * (BB * HH);
            #pragma unroll
            for (int q = 0; q < 4; q++) {
                warp_wait(&g_flagA[t * 4 + q], 128);
                accum_q(acc, sWiA, sWiB, pr, HH, b0, ln, q, true);
            }
        }

        // ---- reduce over the 32-lane K split (padded SMEM transpose) ----
        #pragma unroll
        for (int i = 0; i < 16; i++) {
            float2 v = *reinterpret_cast<float2*>(&acc[i]);
            int a = (i >> 2) * 8 + (i & 3) * 2;
            redw[ln * 33 + a]     = v.x;
            redw[ln * 33 + a + 1] = v.y;
        }
        __syncwarp();
        float s0 = 0.f, s1 = 0.f, s2 = 0.f, s3 = 0.f;
        #pragma unroll
        for (int a = 0; a < 32; a += 4) {
            s0 += redw[(a + 0) * 33 + ln];
            s1 += redw[(a + 1) * 33 + ln];
            s2 += redw[(a + 2) * 33 + ln];
            s3 += redw[(a + 3) * 33 + ln];
        }
        float hval = tanhf((s0 + s1) + (s2 + s3) + bias);

        // ---- publish (per-warp) ----
        if (isA) {
            if (t >= 4) {   // ring slot t&3 reusable once B finished step t-4
                #pragma unroll
                for (int q = 0; q < 4; q++)
                    warp_wait(&g_flagB[(t - 4) * 4 + q], 128);
            }
            g_ring[(t & 3) * (BB * HH) + myb * HH + myc] = hval;
            if (write_final && t == LL - 1)
                out[(long long)BB * LL * HH + myb * HH + myc] = hval;
        } else {
            out[(long long)myb * LL * HH + (long long)t * HH + myc] = hval;
            if (write_final && t == LL - 1)
                out[(long long)BB * LL * HH + BB * HH + myb * HH + myc] = hval;
        }
        __syncwarp();                        // warp's STGs + redw reads done
        if (ln == 0) rel_add(&myflag[t * 4 + qme]);
    }
}

extern "C" void kernel_launch(void* const* d_in, const int* in_sizes, int n_in,
                              void* d_out, int out_size)
{
    const float* x  = (const float*)d_in[0];
    const float* h0 = (const float*)d_in[1];
    const float* Wi = (const float*)d_in[2];
    const float* bi = (const float*)d_in[3];
    const float* Wh = (const float*)d_in[4];
    const float* bh = (const float*)d_in[5];
    float* out = (float*)d_out;

    int write_final = (out_size >= BB * LL * HH + 2 * BB * HH) ? 1 : 0;

    size_t smem = (size_t)(4 * HH * 16) + (size_t)(8 * 32 * 33) * sizeof(float); // ~66 KB
    cudaFuncSetAttribute(rnn_kernel,
                         cudaFuncAttributeMaxDynamicSharedMemorySize, (int)smem);

    zero_flags_kernel<<<(4 * LL + 255) / 256, 256>>>();
    rnn_kernel<<<GA + GB, NTHR, smem>>>(x, h0, Wi, bi, Wh, bh, out, write_final);
}

// round 8
// speedup vs baseline: 1.7239x; 1.7239x over previous
#include <cuda_runtime.h>

// ============================================================================
// 2-layer tanh RNN, B=32, L=2048, H=512 — v7: v5 + collapsed sync RTTs.
//
// 128 persistent CTAs (1/SM):
//   CTA 0..63   : layer 0 (group A), output columns [cta*8, cta*8+8)
//   CTA 64..127 : layer 1 (group B), columns [(cta-64)*8, ...)
// Weight slices in SMEM all run (lane-interleaved, conflict-free LDS.128).
// K mapping: lane ln owns k = 128*i4 + 4*ln + e  (i4 in 0..3, e in 0..3).
//
// Sync v7 (leader-warp polls, CTA barrier releases — v5 primitive):
//   - COMBINED polls: leader spins on 2-3 flag lines in ONE loop (RTTs
//     overlap), single __syncthreads. A: {AL[t-1], AH[t-1], B[t-8]} in one
//     wait. B: {B[t-1], AL[t]} in one wait, then AH[t] alone (split ring
//     waits pipeline A's publish spread against 512 cyc of FMA).
//   - Batched gated loads: accum_both issues all 16 LDG.128 up front
//     (MLP=16, one L2 RTT) before the FMA block.
//   - 8-slot ring (512 KB): reuse check flagB[t-8] has 8 steps of slack,
//     folded into A's combined wait.
// Publish: STG -> __syncthreads -> tid0 red.release.gpu.add (A CTAs 0..31
// bump flagAL[t], 32..63 flagAH[t]; B bumps flagB[t]).
// Compute: fp32 packed fma.rn.f32x2 (512 FMA2/thread/step), numerics as before.
// ============================================================================

#define BB 32
#define LL 2048
#define HH 512
#define GA 64
#define GB 64
#define NTHR 256

__device__ float g_ring[8 * BB * HH];   // layer-0 h ring, 8 slots, 512 KB
__device__ int   g_flagAL[LL];          // A cols [0,256)   done at step t (tgt 32)
__device__ int   g_flagAH[LL];          // A cols [256,512) done at step t (tgt 32)
__device__ int   g_flagB[LL];           // B done at step t (tgt 64)

// Leader-warp combined waits: warp 0 polls all lines each iteration
// (independent acquire loads -> overlapped RTTs); __syncthreads releases CTA.
__device__ __forceinline__ int acq(const int* p) {
    int v;
    asm volatile("ld.acquire.gpu.global.b32 %0, [%1];" : "=r"(v) : "l"(p) : "memory");
    return v;
}
__device__ __forceinline__ void lead_wait1(const int* p1, int t1, int w) {
    if (w == 0) { while (acq(p1) < t1) {} }
    __syncthreads();
}
__device__ __forceinline__ void lead_wait2(const int* p1, int t1,
                                           const int* p2, int t2, int w) {
    if (w == 0) {
        int a, b;
        do { a = acq(p1); b = acq(p2); } while (a < t1 || b < t2);
    }
    __syncthreads();
}
__device__ __forceinline__ void lead_wait3(const int* p1, int t1,
                                           const int* p2, int t2,
                                           const int* p3, int t3, int w) {
    if (w == 0) {
        int a, b, c;
        do { a = acq(p1); b = acq(p2); c = acq(p3); }
        while (a < t1 || b < t2 || c < t3);
    }
    __syncthreads();
}
__device__ __forceinline__ void rel_add(int* p) {
    asm volatile("red.release.gpu.global.add.u32 [%0], %1;"
                 :: "l"(p), "r"(1u) : "memory");
}

#define FMA2(d, a, w) asm volatile("fma.rn.f32x2 %0, %1, %2, %0;" \
                                   : "+l"(d) : "l"(a), "l"(w))

__device__ __forceinline__ unsigned long long pack2(float v) {
    unsigned long long r;
    asm("mov.b64 %0, {%1,%1};" : "=l"(r) : "f"(v));
    return r;
}

__global__ void zero_flags_kernel() {
    int i = blockIdx.x * blockDim.x + threadIdx.x;
    if (i < LL) { g_flagAL[i] = 0; g_flagAH[i] = 0; g_flagB[i] = 0; }
}

// ---- full-K accumulation of one side: ALL 16 LDG.128 batched up front ----
__device__ __forceinline__ void accum_both(
    unsigned long long acc[16],
    const ulonglong2* __restrict__ wA, const ulonglong2* __restrict__ wB,
    const float* __restrict__ p, long long stride, int b0, int ln, bool cg)
{
    float4 v[4][4];   // [i4][b]
    #pragma unroll
    for (int i4 = 0; i4 < 4; i4++)
        #pragma unroll
        for (int b = 0; b < 4; b++) {
            const float4* a = (const float4*)(p + (long long)(b0 + b) * stride
                                              + 128 * i4 + 4 * ln);
            v[i4][b] = cg ? __ldcg(a) : *a;
        }
    #pragma unroll
    for (int i4 = 0; i4 < 4; i4++)
        #pragma unroll
        for (int e = 0; e < 4; e++) {
            ulonglong2 a  = wA[(i4 * 4 + e) * 32 + ln];
            ulonglong2 bq = wB[(i4 * 4 + e) * 32 + ln];
            #pragma unroll
            for (int b = 0; b < 4; b++) {
                float xv = (e == 0) ? v[i4][b].x : (e == 1) ? v[i4][b].y
                         : (e == 2) ? v[i4][b].z : v[i4][b].w;
                unsigned long long xp = pack2(xv);
                FMA2(acc[b * 4 + 0], xp, a.x);
                FMA2(acc[b * 4 + 1], xp, a.y);
                FMA2(acc[b * 4 + 2], xp, bq.x);
                FMA2(acc[b * 4 + 3], xp, bq.y);
            }
        }
}

// ---- half-K accumulation (half = 0: k<256, half = 1: k>=256), 8 loads ----
__device__ __forceinline__ void accum_half(
    unsigned long long acc[16],
    const ulonglong2* __restrict__ wA, const ulonglong2* __restrict__ wB,
    const float* __restrict__ p, long long stride, int b0, int ln,
    int half, bool cg)
{
    float4 v[2][4];
    #pragma unroll
    for (int j = 0; j < 2; j++) {
        int i4 = 2 * half + j;
        #pragma unroll
        for (int b = 0; b < 4; b++) {
            const float4* a = (const float4*)(p + (long long)(b0 + b) * stride
                                              + 128 * i4 + 4 * ln);
            v[j][b] = cg ? __ldcg(a) : *a;
        }
    }
    #pragma unroll
    for (int j = 0; j < 2; j++) {
        int i4 = 2 * half + j;
        #pragma unroll
        for (int e = 0; e < 4; e++) {
            ulonglong2 a  = wA[(i4 * 4 + e) * 32 + ln];
            ulonglong2 bq = wB[(i4 * 4 + e) * 32 + ln];
            #pragma unroll
            for (int b = 0; b < 4; b++) {
                float xv = (e == 0) ? v[j][b].x : (e == 1) ? v[j][b].y
                         : (e == 2) ? v[j][b].z : v[j][b].w;
                unsigned long long xp = pack2(xv);
                FMA2(acc[b * 4 + 0], xp, a.x);
                FMA2(acc[b * 4 + 1], xp, a.y);
                FMA2(acc[b * 4 + 2], xp, bq.x);
                FMA2(acc[b * 4 + 3], xp, bq.y);
            }
        }
    }
}

__global__ __launch_bounds__(NTHR, 1) void rnn_kernel(
    const float* __restrict__ x,   const float* __restrict__ h0in,
    const float* __restrict__ Wi,  const float* __restrict__ bi,
    const float* __restrict__ Wh,  const float* __restrict__ bh,
    float* __restrict__ out, int write_final)
{
    extern __shared__ float smem[];
    ulonglong2* sWiA = (ulonglong2*)smem;      // [512] Wi cols 0-3 (16B each)
    ulonglong2* sWiB = sWiA + HH;              // [512] Wi cols 4-7
    ulonglong2* sWhA = sWiB + HH;
    ulonglong2* sWhB = sWhA + HH;
    float*      red  = (float*)(sWhB + HH);    // [8 warps][32][33]

    const int  cta   = blockIdx.x;
    const bool isA   = (cta < GA);
    const int  layer = isA ? 0 : 1;
    const int  c0    = (isA ? cta : cta - GA) * 8;
    const int  tid   = threadIdx.x;
    const int  w     = tid >> 5;
    const int  ln    = tid & 31;

    // ---- stage weight slices once: idx(k) = ((k>>7)*4 + (k&3))*32 + ((k>>2)&31)
    {
        const float* wi_g = Wi + (size_t)layer * HH * HH + c0;
        const float* wh_g = Wh + (size_t)layer * HH * HH + c0;
        for (int k = tid; k < HH; k += NTHR) {
            int idx = ((k >> 7) * 4 + (k & 3)) * 32 + ((k >> 2) & 31);
            const ulonglong2* ri = (const ulonglong2*)(wi_g + (size_t)k * HH);
            const ulonglong2* rh = (const ulonglong2*)(wh_g + (size_t)k * HH);
            sWiA[idx] = ri[0];  sWiB[idx] = ri[1];
            sWhA[idx] = rh[0];  sWhB[idx] = rh[1];
        }
    }
    __syncthreads();

    const int   myb  = w * 4 + (ln >> 3);
    const int   myc  = c0 + (ln & 7);
    const float bias = bi[layer * HH + myc] + bh[layer * HH + myc];
    const int   b0   = w * 4;
    float* redw = red + w * (32 * 33);

    #pragma unroll 1
    for (int t = 0; t < LL; t++) {
        unsigned long long acc[16];
        #pragma unroll
        for (int i = 0; i < 16; i++) acc[i] = 0ull;

        if (isA) {
            // x-side (ungated) first — hides the wait below.
            accum_both(acc, sWiA, sWiB, x + (long long)t * HH,
                       (long long)LL * HH, b0, ln, false);
            if (t == 0) {
                accum_both(acc, sWhA, sWhB, h0in, HH, b0, ln, false);
            } else {
                // ONE combined wait: own group's t-1 (both halves) + ring
                // slot reuse (flagB[t-8], 8 steps of slack — always ready).
                if (t >= 8)
                    lead_wait3(&g_flagAL[t - 1], 32, &g_flagAH[t - 1], 32,
                               &g_flagB[t - 8], GB, w);
                else
                    lead_wait2(&g_flagAL[t - 1], 32, &g_flagAH[t - 1], 32, w);
                accum_both(acc, sWhA, sWhB,
                           g_ring + ((t - 1) & 7) * (BB * HH), HH, b0, ln, true);
            }
        } else {
            // h1-side: gated on own flagB[t-1] (cheap) — combined with the
            // first ring-half flag so both RTTs overlap.
            if (t == 0) {
                accum_both(acc, sWhA, sWhB, h0in + BB * HH, HH, b0, ln, false);
                lead_wait1(&g_flagAL[0], 32, w);
            } else {
                lead_wait2(&g_flagB[t - 1], GB, &g_flagAL[t], 32, w);
                accum_both(acc, sWhA, sWhB, out + (long long)(t - 1) * HH,
                           (long long)LL * HH, b0, ln, true);
            }
            // ring side: half0 (gated above), then AH wait, half1 —
            // pipelines A's publish spread against 512 cyc of FMA.
            const float* pr = g_ring + (t & 7) * (BB * HH);
            accum_half(acc, sWiA, sWiB, pr, HH, b0, ln, 0, true);
            lead_wait1(&g_flagAH[t], 32, w);
            accum_half(acc, sWiA, sWiB, pr, HH, b0, ln, 1, true);
        }

        // ---- reduce over the 32-lane K split (padded SMEM transpose) ----
        #pragma unroll
        for (int i = 0; i < 16; i++) {
            float2 v = *reinterpret_cast<float2*>(&acc[i]);
            int a = (i >> 2) * 8 + (i & 3) * 2;
            redw[ln * 33 + a]     = v.x;
            redw[ln * 33 + a + 1] = v.y;
        }
        __syncwarp();
        float s0 = 0.f, s1 = 0.f, s2 = 0.f, s3 = 0.f;
        #pragma unroll
        for (int a = 0; a < 32; a += 4) {
            s0 += redw[(a + 0) * 33 + ln];
            s1 += redw[(a + 1) * 33 + ln];
            s2 += redw[(a + 2) * 33 + ln];
            s3 += redw[(a + 3) * 33 + ln];
        }
        float hval = tanhf((s0 + s1) + (s2 + s3) + bias);
        __syncwarp();   // redw reusable next step (warp-private)

        // ---- publish ----
        if (isA) {
            g_ring[(t & 7) * (BB * HH) + myb * HH + myc] = hval;
            if (write_final && t == LL - 1)
                out[(long long)BB * LL * HH + myb * HH + myc] = hval;
        } else {
            out[(long long)myb * LL * HH + (long long)t * HH + myc] = hval;
            if (write_final && t == LL - 1)
                out[(long long)BB * LL * HH + BB * HH + myb * HH + myc] = hval;
        }
        __syncthreads();                 // all STGs of this CTA issued
        if (tid == 0) {
            if (isA) rel_add(cta < 32 ? &g_flagAL[t] : &g_flagAH[t]);
            else     rel_add(&g_flagB[t]);
        }
    }
}

extern "C" void kernel_launch(void* const* d_in, const int* in_sizes, int n_in,
                              void* d_out, int out_size)
{
    const float* x  = (const float*)d_in[0];
    const float* h0 = (const float*)d_in[1];
    const float* Wi = (const float*)d_in[2];
    const float* bi = (const float*)d_in[3];
    const float* Wh = (const float*)d_in[4];
    const float* bh = (const float*)d_in[5];
    float* out = (float*)d_out;

    int write_final = (out_size >= BB * LL * HH + 2 * BB * HH) ? 1 : 0;

    size_t smem = (size_t)(4 * HH * 16) + (size_t)(8 * 32 * 33) * sizeof(float); // ~66 KB
    cudaFuncSetAttribute(rnn_kernel,
                         cudaFuncAttributeMaxDynamicSharedMemorySize, (int)smem);

    zero_flags_kernel<<<(LL + 255) / 256, 256>>>();
    rnn_kernel<<<GA + GB, NTHR, smem>>>(x, h0, Wi, bi, Wh, bh, out, write_final);
}

// round 9
// speedup vs baseline: 1.7679x; 1.0255x over previous
#include <cuda_runtime.h>

// ============================================================================
// 2-layer tanh RNN, B=32, L=2048, H=512 — v8: v7 + K-split warp pairs.
//
// 128 persistent CTAs (1/SM), 512 threads (16 warps):
//   CTA 0..63   : layer 0 (group A), output columns [cta*8, cta*8+8)
//   CTA 64..127 : layer 1 (group B), columns [(cta-64)*8, ...)
// Warp pair (wp, wp+8), wp in 0..7: both handle batch rows 4wp..4wp+3;
//   warp wp   : K-half 0 (k < 256)   — gates on flagAL
//   warp wp+8 : K-half 1 (k >= 256)  — gates on flagAH
// Per-thread FMA2/LDG/LDS all HALVE vs v7; total SM traffic unchanged;
// warps/SMSP 2 -> 4 => latency exposure ~halved.
//
// Sync: two independent half-CTA named barriers (id 1 = low half, id 2 =
// high half, 256 threads each) with leader-warp polls (w0 / w8). Halves
// combine via per-pair named barrier (id 3+wp, 64 thr) + double-buffered
// SMEM. NO CTA-wide barrier in the steady-state loop.
// Publish (low half only): STG -> bar.sync(1,256) -> tid0 red.release.add.
//
// Dataflow: L0 h -> 8-slot global ring; L1 h -> d_out. Cross-SM via __ldcg.
// Compute: fp32 packed fma.rn.f32x2 (256 FMA2/thread/step), numerics as before.
// ============================================================================

#define BB 32
#define LL 2048
#define HH 512
#define GA 64
#define GB 64
#define NTHR 512

__device__ float g_ring[8 * BB * HH];   // layer-0 h ring, 8 slots, 512 KB
__device__ int   g_flagAL[LL];          // A cols [0,256)   done at t (tgt 32)
__device__ int   g_flagAH[LL];          // A cols [256,512) done at t (tgt 32)
__device__ int   g_flagB[LL];           // B done at t (tgt 64)

__device__ __forceinline__ int acq(const int* p) {
    int v;
    asm volatile("ld.acquire.gpu.global.b32 %0, [%1];" : "=r"(v) : "l"(p) : "memory");
    return v;
}
__device__ __forceinline__ void rel_add(int* p) {
    asm volatile("red.release.gpu.global.add.u32 [%0], %1;"
                 :: "l"(p), "r"(1u) : "memory");
}
#define BAR256(id) asm volatile("bar.sync %0, 256;" :: "r"(id) : "memory")
#define BAR64(id)  asm volatile("bar.sync %0, 64;"  :: "r"(id) : "memory")

#define FMA2(d, a, w) asm volatile("fma.rn.f32x2 %0, %1, %2, %0;" \
                                   : "+l"(d) : "l"(a), "l"(w))

__device__ __forceinline__ unsigned long long pack2(float v) {
    unsigned long long r;
    asm("mov.b64 %0, {%1,%1};" : "=l"(r) : "f"(v));
    return r;
}

__global__ void zero_flags_kernel() {
    int i = blockIdx.x * blockDim.x + threadIdx.x;
    if (i < LL) { g_flagAL[i] = 0; g_flagAH[i] = 0; g_flagB[i] = 0; }
}

// Accumulate ONE K-half (hk = 0: k<256, hk = 1: k>=256) of one side into
// acc[16] (acc[b*4+q] packs cols (2q,2q+1) for row b0+b). All 8 LDG.128
// batched up front. Weights lane-interleaved: [(i4*4+e)*32+ln] = k =
// 128*i4 + 4*ln + e.
__device__ __forceinline__ void accum_half(
    unsigned long long acc[16],
    const ulonglong2* __restrict__ wA, const ulonglong2* __restrict__ wB,
    const float* __restrict__ p, long long stride, int b0, int ln,
    int hk, bool cg)
{
    float4 v[2][4];
    #pragma unroll
    for (int j = 0; j < 2; j++) {
        int i4 = 2 * hk + j;
        #pragma unroll
        for (int b = 0; b < 4; b++) {
            const float4* a = (const float4*)(p + (long long)(b0 + b) * stride
                                              + 128 * i4 + 4 * ln);
            v[j][b] = cg ? __ldcg(a) : *a;
        }
    }
    #pragma unroll
    for (int j = 0; j < 2; j++) {
        int i4 = 2 * hk + j;
        #pragma unroll
        for (int e = 0; e < 4; e++) {
            ulonglong2 a  = wA[(i4 * 4 + e) * 32 + ln];
            ulonglong2 bq = wB[(i4 * 4 + e) * 32 + ln];
            #pragma unroll
            for (int b = 0; b < 4; b++) {
                float xv = (e == 0) ? v[j][b].x : (e == 1) ? v[j][b].y
                         : (e == 2) ? v[j][b].z : v[j][b].w;
                unsigned long long xp = pack2(xv);
                FMA2(acc[b * 4 + 0], xp, a.x);
                FMA2(acc[b * 4 + 1], xp, a.y);
                FMA2(acc[b * 4 + 2], xp, bq.x);
                FMA2(acc[b * 4 + 3], xp, bq.y);
            }
        }
    }
}

__global__ __launch_bounds__(NTHR, 1) void rnn_kernel(
    const float* __restrict__ x,   const float* __restrict__ h0in,
    const float* __restrict__ Wi,  const float* __restrict__ bi,
    const float* __restrict__ Wh,  const float* __restrict__ bh,
    float* __restrict__ out, int write_final)
{
    extern __shared__ float smem[];
    ulonglong2* sWiA = (ulonglong2*)smem;      // [512] Wi cols 0-3
    ulonglong2* sWiB = sWiA + HH;              // [512] Wi cols 4-7
    ulonglong2* sWhA = sWiB + HH;
    ulonglong2* sWhB = sWhA + HH;
    float*      red  = (float*)(sWhB + HH);    // [16 warps][32][33]
    float*      comb = red + 16 * 32 * 33;     // [2][8][32] double-buffered

    const int  cta   = blockIdx.x;
    const bool isA   = (cta < GA);
    const int  layer = isA ? 0 : 1;
    const int  c0    = (isA ? cta : cta - GA) * 8;
    const int  tid   = threadIdx.x;
    const int  w     = tid >> 5;
    const int  ln    = tid & 31;
    const int  hk    = w >> 3;          // 0 = low K-half, 1 = high K-half
    const int  wp    = w & 7;           // pair index / low-warp id
    const int  b0    = 4 * wp;

    // ---- stage weight slices once: idx(k) = ((k>>7)*4 + (k&3))*32 + ((k>>2)&31)
    {
        const float* wi_g = Wi + (size_t)layer * HH * HH + c0;
        const float* wh_g = Wh + (size_t)layer * HH * HH + c0;
        for (int k = tid; k < HH; k += NTHR) {
            int idx = ((k >> 7) * 4 + (k & 3)) * 32 + ((k >> 2) & 31);
            const ulonglong2* ri = (const ulonglong2*)(wi_g + (size_t)k * HH);
            const ulonglong2* rh = (const ulonglong2*)(wh_g + (size_t)k * HH);
            sWiA[idx] = ri[0];  sWiB[idx] = ri[1];
            sWhA[idx] = rh[0];  sWhB[idx] = rh[1];
        }
    }
    __syncthreads();    // one-time; loop has no CTA-wide barrier

    const int   myb  = b0 + (ln >> 3);
    const int   myc  = c0 + (ln & 7);
    const float bias = bi[layer * HH + myc] + bh[layer * HH + myc];
    float* redw = red + w * (32 * 33);

    #pragma unroll 1
    for (int t = 0; t < LL; t++) {
        unsigned long long acc[16];
        #pragma unroll
        for (int i = 0; i < 16; i++) acc[i] = 0ull;

        if (isA) {
            // x-side (ungated) first — hides the flag wait below.
            accum_half(acc, sWiA, sWiB, x + (long long)t * HH,
                       (long long)LL * HH, b0, ln, hk, false);
            if (t == 0) {
                accum_half(acc, sWhA, sWhB, h0in, HH, b0, ln, hk, false);
            } else {
                if (hk == 0) {
                    if (w == 0) {
                        if (t >= 8) {
                            while (acq(&g_flagAL[t - 1]) < 32 ||
                                   acq(&g_flagB[t - 8]) < GB) {}
                        } else {
                            while (acq(&g_flagAL[t - 1]) < 32) {}
                        }
                    }
                    BAR256(1);
                } else {
                    if (w == 8) { while (acq(&g_flagAH[t - 1]) < 32) {} }
                    BAR256(2);
                }
                accum_half(acc, sWhA, sWhB,
                           g_ring + ((t - 1) & 7) * (BB * HH), HH, b0, ln, hk, true);
            }
        } else {
            if (t == 0) {
                accum_half(acc, sWhA, sWhB, h0in + BB * HH, HH, b0, ln, hk, false);
                if (hk == 0) {
                    if (w == 0) { while (acq(&g_flagAL[0]) < 32) {} }
                    BAR256(1);
                } else {
                    if (w == 8) { while (acq(&g_flagAH[0]) < 32) {} }
                    BAR256(2);
                }
            } else {
                if (hk == 0) {
                    if (w == 0) {
                        while (acq(&g_flagB[t - 1]) < GB ||
                               acq(&g_flagAL[t]) < 32) {}
                    }
                    BAR256(1);
                } else {
                    if (w == 8) {
                        while (acq(&g_flagB[t - 1]) < GB ||
                               acq(&g_flagAH[t]) < 32) {}
                    }
                    BAR256(2);
                }
                accum_half(acc, sWhA, sWhB, out + (long long)(t - 1) * HH,
                           (long long)LL * HH, b0, ln, hk, true);
            }
            accum_half(acc, sWiA, sWiB, g_ring + (t & 7) * (BB * HH),
                       HH, b0, ln, hk, true);
        }

        // ---- per-warp transpose-reduce over its 32-lane K split ----
        #pragma unroll
        for (int i = 0; i < 16; i++) {
            float2 v = *reinterpret_cast<float2*>(&acc[i]);
            int a = (i >> 2) * 8 + (i & 3) * 2;
            redw[ln * 33 + a]     = v.x;
            redw[ln * 33 + a + 1] = v.y;
        }
        __syncwarp();
        float s0 = 0.f, s1 = 0.f, s2 = 0.f, s3 = 0.f;
        #pragma unroll
        for (int a = 0; a < 32; a += 4) {
            s0 += redw[(a + 0) * 33 + ln];
            s1 += redw[(a + 1) * 33 + ln];
            s2 += redw[(a + 2) * 33 + ln];
            s3 += redw[(a + 3) * 33 + ln];
        }
        float psum = (s0 + s1) + (s2 + s3);
        __syncwarp();   // redw reusable next step (warp-private)

        // ---- combine K-halves (pair barrier), finalize in low warp ----
        if (hk) {
            comb[(t & 1) * 256 + wp * 32 + ln] = psum;
            BAR64(3 + wp);
        } else {
            BAR64(3 + wp);
            float hval = tanhf(psum + comb[(t & 1) * 256 + wp * 32 + ln] + bias);
            if (isA) {
                g_ring[(t & 7) * (BB * HH) + myb * HH + myc] = hval;
                if (write_final && t == LL - 1)
                    out[(long long)BB * LL * HH + myb * HH + myc] = hval;
            } else {
                out[(long long)myb * LL * HH + (long long)t * HH + myc] = hval;
                if (write_final && t == LL - 1)
                    out[(long long)BB * LL * HH + BB * HH + myb * HH + myc] = hval;
            }
            BAR256(1);                      // low half: all STGs issued
            if (tid == 0) {
                if (isA) rel_add(cta < 32 ? &g_flagAL[t] : &g_flagAH[t]);
                else     rel_add(&g_flagB[t]);
            }
        }
    }
}

extern "C" void kernel_launch(void* const* d_in, const int* in_sizes, int n_in,
                              void* d_out, int out_size)
{
    const float* x  = (const float*)d_in[0];
    const float* h0 = (const float*)d_in[1];
    const float* Wi = (const float*)d_in[2];
    const float* bi = (const float*)d_in[3];
    const float* Wh = (const float*)d_in[4];
    const float* bh = (const float*)d_in[5];
    float* out = (float*)d_out;

    int write_final = (out_size >= BB * LL * HH + 2 * BB * HH) ? 1 : 0;

    size_t smem = (size_t)(4 * HH * 16)                    // weights 32 KB
                + (size_t)(16 * 32 * 33) * sizeof(float)   // red    ~66 KB
                + (size_t)(2 * 8 * 32) * sizeof(float);    // comb     2 KB
    cudaFuncSetAttribute(rnn_kernel,
                         cudaFuncAttributeMaxDynamicSharedMemorySize, (int)smem);

    zero_flags_kernel<<<(LL + 255) / 256, 256>>>();
    rnn_kernel<<<GA + GB, NTHR, smem>>>(x, h0, Wi, bi, Wh, bh, out, write_final);
}